// round 16
// baseline (speedup 1.0000x reference)
#include <cuda_runtime.h>
#include <cstdint>

// ACT-LSTM persistent kernel, v11.
// vs v10: TRIPLE-buffered cp.async.bulk pipeline (3x64KB stages in flight)
// for the fused t=0 pass, and phase A (per-step W_hh matvec) ALSO streams
// through the same bulk pipeline (8 stages) instead of register-limited LDG.
// mbarrier parity derived from a global stage counter shared across phases.
//
// I=1024, H=2048, O=1024, 4H=8192, MAX_STEPS=20.

#define NBLOCK 128
#define NTHREAD 1024
#define WPB 32
#define HDIM 2048
#define IDIM 1024
#define ODIM 1024
#define G4 (4 * HDIM)
#define MAX_STEPS 20
#define RPB 64                    // gate rows per block
#define IH_STG_FLOATS (16 * 1025) // 16400 (16 rows incl flag col)
#define HH_STG_FLOATS (8 * 2048)  // 16384 (8 rows)
#define BUF_FLOATS IH_STG_FLOATS
#define NBUF 3
#define NSTG_T0 12                // 4 W_ih + 8 W_hh

// smem (floats): 3 bufs + sh_h + sh_c + sh_x + s_ih2[128] + s_hh4[256]
//                + s_flag[64] + s_red[32] + mbar pad[8]
#define SMEM_FLOATS (NBUF * BUF_FLOATS + HDIM + HDIM + IDIM + 128 + 256 + 64 + 32 + 8)
#define SMEM_BYTES (SMEM_FLOATS * 4)

__device__ float g_gates[2][G4];
__device__ float g_gx_buf[G4];

__device__ unsigned g_bar_count = 0;
__device__ volatile unsigned g_bar_gen = 0;

__device__ __forceinline__ void grid_sync() {
    __syncthreads();
    if (threadIdx.x == 0) {
        __threadfence();
        unsigned gen = g_bar_gen;
        if (atomicAdd(&g_bar_count, 1u) == NBLOCK - 1) {
            g_bar_count = 0u;
            __threadfence();
            g_bar_gen = gen + 1u;
        } else {
            while (g_bar_gen == gen) { __nanosleep(32); }
            __threadfence();
        }
    }
    __syncthreads();
}

__device__ __forceinline__ float warp_reduce(float v) {
    #pragma unroll
    for (int off = 16; off; off >>= 1) v += __shfl_xor_sync(0xffffffffu, v, off);
    return v;
}

__device__ __forceinline__ float sigmoidf_(float x) {
    return 1.0f / (1.0f + __expf(-x));
}

__device__ __forceinline__ float dot4(float4 a, float4 b) {
    return a.x * b.x + a.y * b.y + a.z * b.z + a.w * b.w;
}

__device__ __forceinline__ void mbar_init(uint32_t mb, uint32_t count) {
    asm volatile("mbarrier.init.shared.b64 [%0], %1;" :: "r"(mb), "r"(count) : "memory");
}
__device__ __forceinline__ void mbar_expect_tx(uint32_t mb, uint32_t bytes) {
    asm volatile("mbarrier.arrive.expect_tx.shared.b64 _, [%0], %1;"
                 :: "r"(mb), "r"(bytes) : "memory");
}
__device__ __forceinline__ void bulk_g2s(uint32_t dst, const void* src,
                                         uint32_t bytes, uint32_t mb) {
    asm volatile("cp.async.bulk.shared::cta.global.mbarrier::complete_tx::bytes "
                 "[%0], [%1], %2, [%3];"
                 :: "r"(dst), "l"(src), "r"(bytes), "r"(mb) : "memory");
}
__device__ __forceinline__ void mbar_wait(uint32_t mb, uint32_t parity) {
    uint32_t done;
    asm volatile(
        "{\n\t.reg .pred p;\n\t"
        "mbarrier.try_wait.parity.acquire.cta.shared::cta.b64 p, [%1], %2;\n\t"
        "selp.b32 %0, 1, 0, p;\n\t}"
        : "=r"(done) : "r"(mb), "r"(parity) : "memory");
    if (!done) {
        asm volatile(
            "{\n\t.reg .pred P1;\n\t"
            "W_%=:\n\t"
            "mbarrier.try_wait.parity.acquire.cta.shared::cta.b64 P1, [%0], %1, 0x989680;\n\t"
            "@P1 bra.uni D_%=;\n\t"
            "bra.uni W_%=;\n\t"
            "D_%=:\n\t}"
            :: "r"(mb), "r"(parity) : "memory");
    }
}

__global__ __launch_bounds__(NTHREAD, 1)
void act_lstm_kernel(const float* __restrict__ x,
                     const float* __restrict__ h0,
                     const float* __restrict__ c0,
                     const float* __restrict__ W_ih,
                     const float* __restrict__ W_hh,
                     const float* __restrict__ b_ih,
                     const float* __restrict__ b_hh,
                     const float* __restrict__ w_halt,
                     const float* __restrict__ b_halt,
                     const float* __restrict__ W_out,
                     const float* __restrict__ b_out,
                     float* __restrict__ out) {
    extern __shared__ float smem[];
    float* bufs   = smem;                        // NBUF * BUF_FLOATS
    float* sh_h   = smem + NBUF * BUF_FLOATS;
    float* sh_c   = sh_h + HDIM;
    float* sh_x   = sh_c + HDIM;
    float* s_ih2  = sh_x + IDIM;       // [RPB*2]
    float* s_hh4  = s_ih2 + 128;       // [RPB*4]
    float* s_flag = s_hh4 + 256;       // [RPB]
    float* s_red  = s_flag + 64;       // [32]
    float* s_mbar = s_red + 32;        // 3x u64

    const int tid  = threadIdx.x;
    const int lane = tid & 31;
    const int warp = tid >> 5;
    const int bx   = blockIdx.x;
    const int r0blk = bx * RPB;

    const uint32_t mbbase  = (uint32_t)__cvta_generic_to_shared(s_mbar);
    const uint32_t bufbase = (uint32_t)__cvta_generic_to_shared(bufs);

    // ---- init state + mbarriers ----
    for (int j = tid; j < HDIM; j += NTHREAD) {
        sh_h[j] = h0[j];
        sh_c[j] = c0[j];
    }
    if (tid < IDIM) sh_x[tid] = x[tid];
    if (tid == 0) {
        mbar_init(mbbase, 1);
        mbar_init(mbbase + 8, 1);
        mbar_init(mbbase + 16, 1);
    }
    const float bh = b_halt[0];
    __syncthreads();

    // issue bulk copy for global stage G; kind 0 = W_ih stage idx, 1 = W_hh
    auto issue = [&](int G, int kind, int idx) {
        if (tid != 0) return;
        const int slot = G % NBUF;
        const uint32_t mb  = mbbase + slot * 8;
        const uint32_t dst = bufbase + slot * (BUF_FLOATS * 4);
        const float* src;
        uint32_t bytes;
        if (kind == 0) {
            src = W_ih + (size_t)bx * (RPB * (IDIM + 1)) + (size_t)idx * IH_STG_FLOATS;
            bytes = IH_STG_FLOATS * 4;
        } else {
            src = W_hh + ((size_t)r0blk + 8 * idx) * HDIM;
            bytes = HH_STG_FLOATS * 4;
        }
        mbar_expect_tx(mb, bytes);
        bulk_g2s(dst, src, bytes, mb);
    };
    auto wait_stage = [&](int G) {
        const int slot = G % NBUF;
        mbar_wait(mbbase + slot * 8, (uint32_t)((G / NBUF) & 1));
    };

    // ================== fused t=0 pass: 12 stages, 3-deep ==================
    issue(0, 0, 0);
    issue(1, 0, 1);
    issue(2, 0, 2);
    for (int s = 0; s < NSTG_T0; ++s) {
        wait_stage(s);
        const float* bp = bufs + (s % NBUF) * BUF_FLOATS;
        if (s < 4) {
            // 16 W_ih rows x 1025; 2 warps/row, 512 cols each
            const int rl = warp >> 1;
            const int hf = warp & 1;
            const float* rowp = bp + rl * 1025;
            const float* p  = rowp + 1 + hf * 512 + lane;
            const float* xs = sh_x + hf * 512 + lane;
            float a = 0.f;
            #pragma unroll
            for (int i = 0; i < 16; ++i) a += p[i * 32] * xs[i * 32];
            a = warp_reduce(a);
            if (lane == 0) s_ih2[(16 * s + rl) * 2 + hf] = a;
            if (lane == 1 && hf == 0) s_flag[16 * s + rl] = rowp[0];
        } else {
            // 8 W_hh rows x 2048; 4 warps/row, 512 cols each
            const int s2 = s - 4;
            const int rl = warp >> 2;
            const int q  = warp & 3;
            const float4* w4 = (const float4*)(bp + rl * HDIM + q * 512);
            const float4* h4 = (const float4*)(sh_h + q * 512);
            float a = 0.f;
            #pragma unroll
            for (int i = 0; i < 4; ++i)
                a += dot4(w4[lane + i * 32], h4[lane + i * 32]);
            a = warp_reduce(a);
            if (lane == 0) s_hh4[(8 * s2 + rl) * 4 + q] = a;
        }
        __syncthreads();
        if (s + 3 < NSTG_T0) {
            const int G = s + 3;
            issue(G, G < 4 ? 0 : 1, G < 4 ? G : G - 4);
        }
    }

    if (tid < RPB) {
        const int r = r0blk + tid;
        float ih = s_ih2[tid * 2] + s_ih2[tid * 2 + 1] + b_ih[r] + b_hh[r];
        float hh = (s_hh4[tid * 4] + s_hh4[tid * 4 + 1])
                 + (s_hh4[tid * 4 + 2] + s_hh4[tid * 4 + 3]);
        g_gx_buf[r] = ih;
        g_gates[0][r] = ih + s_flag[tid] + hh;
    }
    grid_sync();

    // ================== adaptive loop: ONE grid barrier/step ==================
    float cum = 0.0f;
    int   halted_t = MAX_STEPS - 1;
    int   gbuf = 0;
    int   gstage = NSTG_T0;          // global bulk-stage counter (parity)

    for (int t = 0; t < MAX_STEPS; ++t) {
        // phase B: activations + halt
        const float* gt = g_gates[gbuf];
        float part = 0.0f;
        #pragma unroll
        for (int j = tid; j < HDIM; j += NTHREAD) {
            float gi = gt[j];
            float gf = gt[HDIM + j];
            float gg = gt[2 * HDIM + j];
            float go = gt[3 * HDIM + j];
            float cn = sigmoidf_(gf) * sh_c[j] + sigmoidf_(gi) * tanhf(gg);
            float hn = sigmoidf_(go) * tanhf(cn);
            sh_c[j] = cn;
            sh_h[j] = hn;
            part += w_halt[j] * hn;
        }
        part = warp_reduce(part);
        if (lane == 0) s_red[warp] = part;
        __syncthreads();
        float dot = 0.0f;
        #pragma unroll
        for (int w2 = 0; w2 < WPB; ++w2) dot += s_red[w2];
        float p = sigmoidf_(dot + bh);
        cum += p;
        if (cum >= 0.99f || t == MAX_STEPS - 1) { halted_t = t; break; }

        // phase A for t+1: bulk-pipelined W_hh @ h (8 stages)
        gbuf ^= 1;
        float* gn = g_gates[gbuf];
        issue(gstage + 0, 1, 0);
        issue(gstage + 1, 1, 1);
        issue(gstage + 2, 1, 2);
        for (int i = 0; i < 8; ++i) {
            wait_stage(gstage + i);
            const float* bp = bufs + ((gstage + i) % NBUF) * BUF_FLOATS;
            const int rl = warp >> 2;
            const int q  = warp & 3;
            const float4* w4 = (const float4*)(bp + rl * HDIM + q * 512);
            const float4* h4 = (const float4*)(sh_h + q * 512);
            float a = 0.f;
            #pragma unroll
            for (int k = 0; k < 4; ++k)
                a += dot4(w4[lane + k * 32], h4[lane + k * 32]);
            a = warp_reduce(a);
            if (lane == 0) s_hh4[(8 * i + rl) * 4 + q] = a;
            __syncthreads();
            if (i + 3 < 8) issue(gstage + i + 3, 1, i + 3);
        }
        gstage += 8;
        if (tid < RPB) {
            const int r = r0blk + tid;
            gn[r] = g_gx_buf[r]
                  + (s_hh4[tid * 4] + s_hh4[tid * 4 + 1])
                  + (s_hh4[tid * 4 + 2] + s_hh4[tid * 4 + 3]);
        }
        grid_sync();
    }

    // ================== epilogue: out = W_out @ h + b_out ==================
    __syncthreads();
    {
        const int gwarp = bx * WPB + warp;
        const int row = gwarp >> 2;
        const int q   = gwarp & 3;
        const float4* wr = (const float4*)(W_out + (size_t)row * HDIM) + q * (HDIM / 16);
        const float4* hv = (const float4*)sh_h + q * (HDIM / 16);
        float a = 0.f;
        #pragma unroll 4
        for (int k = lane; k < HDIM / 16; k += 32) {
            float4 w  = __ldg(wr + k);
            float4 h4 = hv[k];
            a += dot4(w, h4);
        }
        a = warp_reduce(a);
        if (lane == 0) s_red[warp] = a;
        __syncthreads();
        if ((warp & 3) == 0 && lane == 0) {
            out[row] = s_red[warp] + s_red[warp + 1] + s_red[warp + 2]
                     + s_red[warp + 3] + b_out[row];
        }
    }

    if (bx == 0) {
        for (int j = tid; j < HDIM; j += NTHREAD) {
            out[ODIM + j]        = sh_h[j];
            out[ODIM + HDIM + j] = sh_c[j];
        }
        if (tid == 0) out[ODIM + 2 * HDIM] = (float)halted_t;
    }
}

extern "C" void kernel_launch(void* const* d_in, const int* in_sizes, int n_in,
                              void* d_out, int out_size) {
    (void)in_sizes; (void)n_in; (void)out_size;
    const float* x      = (const float*)d_in[0];
    const float* h0     = (const float*)d_in[1];
    const float* c0     = (const float*)d_in[2];
    const float* W_ih   = (const float*)d_in[3];
    const float* W_hh   = (const float*)d_in[4];
    const float* b_ih   = (const float*)d_in[5];
    const float* b_hh   = (const float*)d_in[6];
    const float* w_halt = (const float*)d_in[7];
    const float* b_halt = (const float*)d_in[8];
    const float* W_out  = (const float*)d_in[9];
    const float* b_out  = (const float*)d_in[10];
    float* out = (float*)d_out;

    cudaFuncSetAttribute(act_lstm_kernel,
                         cudaFuncAttributeMaxDynamicSharedMemorySize, SMEM_BYTES);
    act_lstm_kernel<<<NBLOCK, NTHREAD, SMEM_BYTES>>>(x, h0, c0, W_ih, W_hh,
                                                     b_ih, b_hh, w_halt, b_halt,
                                                     W_out, b_out, out);
}

// round 17
// speedup vs baseline: 1.3032x; 1.3032x over previous
#include <cuda_runtime.h>

// ACT-LSTM persistent kernel, v12 = v4's proven consumption pattern
// (2 concurrent row chains per warp, plain LDG) remapped onto all 148 SMs
// with balanced contiguous row chunks (55-56 rows/block, 676KB/SM vs 780KB).
// Warps 0-23 carry 2 rows, 24-31 carry 1 (aliased to row 0, discarded) --
// critical path unchanged, 13% fewer bytes per SM, 20 more SMs streaming.
// Epilogue spread over 148 blocks (v6 scheme). Everything else = v4.
//
// I=1024, H=2048, O=1024, 4H=8192, MAX_STEPS=20.

#define NBLOCK 148
#define NTHREAD 1024
#define WPB 32
#define HDIM 2048
#define IDIM 1024
#define ODIM 1024
#define G4 (4 * HDIM)
#define MAX_STEPS 20

// -------- device scratch --------
__device__ float g_gates[2][G4];
__device__ float g_gx_buf[G4];

// -------- manual grid barrier --------
__device__ unsigned g_bar_count = 0;
__device__ volatile unsigned g_bar_gen = 0;

__device__ __forceinline__ void grid_sync() {
    __syncthreads();
    if (threadIdx.x == 0) {
        __threadfence();
        unsigned gen = g_bar_gen;
        if (atomicAdd(&g_bar_count, 1u) == NBLOCK - 1) {
            g_bar_count = 0u;
            __threadfence();
            g_bar_gen = gen + 1u;
        } else {
            while (g_bar_gen == gen) { __nanosleep(32); }
            __threadfence();
        }
    }
    __syncthreads();
}

__device__ __forceinline__ float warp_reduce(float v) {
    #pragma unroll
    for (int off = 16; off; off >>= 1) v += __shfl_xor_sync(0xffffffffu, v, off);
    return v;
}

__device__ __forceinline__ float sigmoidf_(float x) {
    return 1.0f / (1.0f + __expf(-x));
}

__device__ __forceinline__ float dot4(float4 a, float4 b) {
    return a.x * b.x + a.y * b.y + a.z * b.z + a.w * b.w;
}

__global__ __launch_bounds__(NTHREAD, 1)
void act_lstm_kernel(const float* __restrict__ x,
                     const float* __restrict__ h0,
                     const float* __restrict__ c0,
                     const float* __restrict__ W_ih,
                     const float* __restrict__ W_hh,
                     const float* __restrict__ b_ih,
                     const float* __restrict__ b_hh,
                     const float* __restrict__ w_halt,
                     const float* __restrict__ b_halt,
                     const float* __restrict__ W_out,
                     const float* __restrict__ b_out,
                     float* __restrict__ out) {
    __shared__ float sh_h[HDIM];
    __shared__ float sh_c[HDIM];
    __shared__ float sh_x[IDIM];
    __shared__ float s_red[WPB];

    const int tid  = threadIdx.x;
    const int lane = tid & 31;
    const int warp = tid >> 5;
    const int bx   = blockIdx.x;

    // balanced contiguous row chunk: 52 blocks x 56 rows, 96 x 55
    const int nrows = 55 + (bx < 52 ? 1 : 0);
    const int chunk = bx * 55 + (bx < 52 ? bx : 52);

    // warp's two rows (second aliased to chunk row 0 when absent; discarded)
    const int  r0   = chunk + warp;
    const bool has1 = (warp + 32) < nrows;
    const int  r1   = has1 ? (chunk + warp + 32) : chunk;

    // ---- init block-local state ----
    for (int j = tid; j < HDIM; j += NTHREAD) {
        sh_h[j] = h0[j];
        sh_c[j] = c0[j];
    }
    if (tid < IDIM) sh_x[tid] = x[tid];
    const float bh = b_halt[0];
    __syncthreads();

    // ---- fused phase: gates(t=0) = W_ih@[1,x] + b_ih + b_hh + W_hh@h0 ----
    {
        const float* wi0 = W_ih + (size_t)r0 * (IDIM + 1);
        const float* wi1 = W_ih + (size_t)r1 * (IDIM + 1);
        float ai0 = 0.f, ai1 = 0.f;
        #pragma unroll 8
        for (int k = lane; k < IDIM; k += 32) {
            float xv = sh_x[k];
            ai0 += __ldg(wi0 + 1 + k) * xv;
            ai1 += __ldg(wi1 + 1 + k) * xv;
        }

        const float4* wh0 = (const float4*)(W_hh + (size_t)r0 * HDIM);
        const float4* wh1 = (const float4*)(W_hh + (size_t)r1 * HDIM);
        const float4* hv  = (const float4*)sh_h;
        float ah0 = 0.f, ah1 = 0.f;
        #pragma unroll 4
        for (int k = lane; k < HDIM / 4; k += 32) {
            float4 h4 = hv[k];
            float4 w0 = __ldg(wh0 + k);
            float4 w1 = __ldg(wh1 + k);
            ah0 += dot4(w0, h4);
            ah1 += dot4(w1, h4);
        }

        ai0 = warp_reduce(ai0); ai1 = warp_reduce(ai1);
        ah0 = warp_reduce(ah0); ah1 = warp_reduce(ah1);

        if (lane == 0) {
            float b0 = ai0 + b_ih[r0] + b_hh[r0];
            g_gx_buf[r0] = b0;
            g_gates[0][r0] = b0 + __ldg(wi0) + ah0;   // flag col at t=0
            if (has1) {
                float b1 = ai1 + b_ih[r1] + b_hh[r1];
                g_gx_buf[r1] = b1;
                g_gates[0][r1] = b1 + __ldg(wi1) + ah1;
            }
        }
    }
    grid_sync();

    // ---- adaptive loop: ONE grid barrier per step ----
    float cum = 0.0f;
    int   halted_t = MAX_STEPS - 1;
    int   buf = 0;

    for (int t = 0; t < MAX_STEPS; ++t) {
        // phase B: activations + halt (redundant per block, block-local state)
        const float* gt = g_gates[buf];
        float part = 0.0f;
        #pragma unroll
        for (int j = tid; j < HDIM; j += NTHREAD) {
            float gi = gt[j];
            float gf = gt[HDIM + j];
            float gg = gt[2 * HDIM + j];
            float go = gt[3 * HDIM + j];
            float cn = sigmoidf_(gf) * sh_c[j] + sigmoidf_(gi) * tanhf(gg);
            float hn = sigmoidf_(go) * tanhf(cn);
            sh_c[j] = cn;
            sh_h[j] = hn;
            part += w_halt[j] * hn;
        }
        part = warp_reduce(part);
        if (lane == 0) s_red[warp] = part;
        __syncthreads();
        float dot = 0.0f;
        #pragma unroll
        for (int w2 = 0; w2 < WPB; ++w2) dot += s_red[w2];
        float p = sigmoidf_(dot + bh);
        cum += p;
        if (cum >= 0.99f || t == MAX_STEPS - 1) { halted_t = t; break; }

        // phase A for step t+1: gates = gx + W_hh @ h (2 concurrent chains)
        buf ^= 1;
        float* gn = g_gates[buf];
        {
            const float4* wh0 = (const float4*)(W_hh + (size_t)r0 * HDIM);
            const float4* wh1 = (const float4*)(W_hh + (size_t)r1 * HDIM);
            const float4* hv  = (const float4*)sh_h;
            float ah0 = 0.f, ah1 = 0.f;
            #pragma unroll 4
            for (int k = lane; k < HDIM / 4; k += 32) {
                float4 h4 = hv[k];
                float4 w0 = __ldg(wh0 + k);
                float4 w1 = __ldg(wh1 + k);
                ah0 += dot4(w0, h4);
                ah1 += dot4(w1, h4);
            }
            ah0 = warp_reduce(ah0);
            ah1 = warp_reduce(ah1);
            if (lane == 0) {
                gn[r0] = g_gx_buf[r0] + ah0;
                if (has1) gn[r1] = g_gx_buf[r1] + ah1;
            }
        }
        grid_sync();
    }

    // ---- epilogue (barrier-free): out = W_out @ h + b_out ----
    // 1024 rows over 148 blocks: 136 x 7, 12 x 6; 4 warps per row (k-quarter).
    __syncthreads();
    {
        const int orows  = 6 + (bx < 136 ? 1 : 0);
        const int ostart = bx * 6 + (bx < 136 ? bx : 136);
        const int ounits = orows * 4;            // 24 or 28 <= 32
        if (warp < ounits) {
            const int row = ostart + (warp >> 2);
            const int q   = warp & 3;
            const float4* wr = (const float4*)(W_out + (size_t)row * HDIM) + q * (HDIM / 16);
            const float4* hv = (const float4*)sh_h + q * (HDIM / 16);
            float a = 0.f;
            #pragma unroll 4
            for (int k = lane; k < HDIM / 16; k += 32) {
                float4 w  = __ldg(wr + k);
                float4 h4 = hv[k];
                a += dot4(w, h4);
            }
            a = warp_reduce(a);
            if (lane == 0) s_red[warp] = a;
        }
        __syncthreads();
        if (tid < orows) {
            const int row = ostart + tid;
            out[row] = (s_red[4 * tid] + s_red[4 * tid + 1])
                     + (s_red[4 * tid + 2] + s_red[4 * tid + 3]) + b_out[row];
        }
    }

    if (bx == 0) {
        for (int j = tid; j < HDIM; j += NTHREAD) {
            out[ODIM + j]        = sh_h[j];
            out[ODIM + HDIM + j] = sh_c[j];
        }
        if (tid == 0) out[ODIM + 2 * HDIM] = (float)halted_t;
    }
}

extern "C" void kernel_launch(void* const* d_in, const int* in_sizes, int n_in,
                              void* d_out, int out_size) {
    (void)in_sizes; (void)n_in; (void)out_size;
    const float* x      = (const float*)d_in[0];
    const float* h0     = (const float*)d_in[1];
    const float* c0     = (const float*)d_in[2];
    const float* W_ih   = (const float*)d_in[3];
    const float* W_hh   = (const float*)d_in[4];
    const float* b_ih   = (const float*)d_in[5];
    const float* b_hh   = (const float*)d_in[6];
    const float* w_halt = (const float*)d_in[7];
    const float* b_halt = (const float*)d_in[8];
    const float* W_out  = (const float*)d_in[9];
    const float* b_out  = (const float*)d_in[10];
    float* out = (float*)d_out;

    act_lstm_kernel<<<NBLOCK, NTHREAD>>>(x, h0, c0, W_ih, W_hh, b_ih, b_hh,
                                         w_halt, b_halt, W_out, b_out, out);
}